// round 1
// baseline (speedup 1.0000x reference)
#include <cuda_runtime.h>
#include <math.h>

// ---------------- problem constants ----------------
#define BB      4
#define LL      2048
#define DM      1024          // d_model
#define DI      2048          // d_inner
#define DS      16            // d_state
#define DTR     64            // dt_rank
#define ROWS    (BB*LL)       // 8192 token rows
#define DBC_LD  128           // padded (dt_rank + 2*d_state = 96 -> 128)

// ---------------- scratch (static device memory; no cudaMalloc allowed) ----
__device__ float g_xn [ (size_t)ROWS*DM ];        // 32 MB
__device__ float g_xz [ (size_t)ROWS*2*DI ];      // 128 MB  (u | z)
__device__ float g_uc [ (size_t)ROWS*DI ];        // 64 MB
__device__ float g_wxp[ (size_t)DI*DBC_LD ];      // 1 MB (padded W_x)
__device__ float g_dbc[ (size_t)ROWS*DBC_LD ];    // 4 MB
__device__ float g_dt [ (size_t)ROWS*DI ];        // 64 MB
__device__ float g_yg [ (size_t)ROWS*DI ];        // 64 MB

// ---------------- LayerNorm ----------------
__global__ void __launch_bounds__(256) ln_kernel(
    const float* __restrict__ x, const float* __restrict__ g,
    const float* __restrict__ b, float* __restrict__ out)
{
    int row = blockIdx.x;
    int tid = threadIdx.x;
    const float4* xr = (const float4*)(x + (size_t)row*DM);
    float4 v = xr[tid];                       // 256 threads * 4 = 1024
    float s  = v.x + v.y + v.z + v.w;
    float ss = v.x*v.x + v.y*v.y + v.z*v.z + v.w*v.w;
    #pragma unroll
    for (int o = 16; o; o >>= 1) {
        s  += __shfl_xor_sync(0xffffffffu, s,  o);
        ss += __shfl_xor_sync(0xffffffffu, ss, o);
    }
    __shared__ float sb[8], ssb[8];
    if ((tid & 31) == 0) { sb[tid>>5] = s; ssb[tid>>5] = ss; }
    __syncthreads();
    float tot = 0.f, tot2 = 0.f;
    #pragma unroll
    for (int i = 0; i < 8; i++) { tot += sb[i]; tot2 += ssb[i]; }
    float mu  = tot * (1.0f/DM);
    float var = tot2 * (1.0f/DM) - mu*mu;
    float rs  = rsqrtf(var + 1e-5f);
    float4 gv = ((const float4*)g)[tid];
    float4 bv = ((const float4*)b)[tid];
    float4 o;
    o.x = (v.x-mu)*rs*gv.x + bv.x;
    o.y = (v.y-mu)*rs*gv.y + bv.y;
    o.z = (v.z-mu)*rs*gv.z + bv.z;
    o.w = (v.w-mu)*rs*gv.w + bv.w;
    ((float4*)(out + (size_t)row*DM))[tid] = o;
}

// ---------------- pad W_x (2048x96) into (2048x128) ----------------
__global__ void pad_wx_kernel(const float* __restrict__ wx, float* __restrict__ out)
{
    int idx = blockIdx.x * blockDim.x + threadIdx.x;
    if (idx >= DI * DBC_LD) return;
    int r = idx / DBC_LD, c = idx % DBC_LD;
    out[idx] = (c < 96) ? wx[r*96 + c] : 0.f;
}

// ---------------- depthwise causal conv (k=4) + SiLU ----------------
__global__ void __launch_bounds__(256) conv_silu_kernel(
    const float* __restrict__ xz, const float* __restrict__ w,
    const float* __restrict__ cb, float* __restrict__ uc)
{
    int idx = blockIdx.x * blockDim.x + threadIdx.x;
    if (idx >= ROWS*DI) return;
    int d   = idx % DI;
    int row = idx / DI;           // b*L + l
    int l   = row % LL;
    const float* up = xz + (size_t)row*(2*DI) + d;   // u-half of xz
    float4 wv = *(const float4*)(w + d*4);
    float acc = cb[d];
    if (l >= 3) acc += wv.x * up[-3*2*DI];
    if (l >= 2) acc += wv.y * up[-2*2*DI];
    if (l >= 1) acc += wv.z * up[-1*2*DI];
    acc += wv.w * up[0];
    uc[idx] = acc / (1.f + __expf(-acc));
}

// ---------------- SGEMM 128x128x8, 8x8/thread, templated epilogue --------
// EPI: 0 = plain store, 1 = softplus(acc + bias[n]), 2 = acc + res[m][n]
__device__ __forceinline__ float softplus_f(float x) {
    return (x > 20.f) ? x : log1pf(__expf(x));
}

template<int EPI>
__global__ void __launch_bounds__(256) sgemm_kernel(
    int M, int N, int K,
    const float* __restrict__ A, int lda,
    const float* __restrict__ B, int ldb,
    float* __restrict__ C, int ldc,
    const float* __restrict__ bias,
    const float* __restrict__ res, int ldr)
{
    constexpr int BM = 128, BN = 128, BK = 8, TM = 8, TN = 8;
    __shared__ float As[BK][BM];
    __shared__ float Bs[BK][BN];

    int tid  = threadIdx.x;
    int brow = blockIdx.y, bcol = blockIdx.x;
    A += (size_t)brow * BM * lda;
    B += (size_t)bcol * BN;

    int arow   = tid >> 1;            // 0..127
    int acol   = (tid & 1) * 4;       // 0 or 4
    int brow_l = tid >> 5;            // 0..7
    int bcol_l = (tid & 31) * 4;      // 0..124
    int tr = (tid >> 4) * TM;         // 16x16 thread grid
    int tc = (tid & 15) * TN;

    float acc[TM][TN] = {};
    float ar[TM], br[TN];

    for (int k0 = 0; k0 < K; k0 += BK) {
        float4 av = *(const float4*)(A + (size_t)arow*lda + k0 + acol);
        As[acol+0][arow] = av.x;
        As[acol+1][arow] = av.y;
        As[acol+2][arow] = av.z;
        As[acol+3][arow] = av.w;
        float4 bv = *(const float4*)(B + (size_t)(k0 + brow_l)*ldb + bcol_l);
        *(float4*)(&Bs[brow_l][bcol_l]) = bv;
        __syncthreads();
        #pragma unroll
        for (int kk = 0; kk < BK; kk++) {
            #pragma unroll
            for (int i = 0; i < TM; i++) ar[i] = As[kk][tr+i];
            #pragma unroll
            for (int j = 0; j < TN; j++) br[j] = Bs[kk][tc+j];
            #pragma unroll
            for (int i = 0; i < TM; i++)
                #pragma unroll
                for (int j = 0; j < TN; j++)
                    acc[i][j] = fmaf(ar[i], br[j], acc[i][j]);
        }
        __syncthreads();
    }

    int crow0 = brow*BM + tr;
    int ccol0 = bcol*BN + tc;
    #pragma unroll
    for (int i = 0; i < TM; i++) {
        float* crow = C + (size_t)(crow0+i)*ldc + ccol0;
        #pragma unroll
        for (int j = 0; j < TN; j += 4) {
            float4 v = make_float4(acc[i][j], acc[i][j+1], acc[i][j+2], acc[i][j+3]);
            if (EPI == 1) {
                float4 bb = *(const float4*)(bias + ccol0 + j);
                v.x = softplus_f(v.x + bb.x);
                v.y = softplus_f(v.y + bb.y);
                v.z = softplus_f(v.z + bb.z);
                v.w = softplus_f(v.w + bb.w);
            } else if (EPI == 2) {
                float4 r = *(const float4*)(res + (size_t)(crow0+i)*ldr + ccol0 + j);
                v.x += r.x; v.y += r.y; v.z += r.z; v.w += r.w;
            }
            *(float4*)(crow + j) = v;
        }
    }
}

// ---------------- selective scan (serial in L) + gating ----------------
// 4 threads per channel (4 states each); 64 channels per block (256 thr).
__global__ void __launch_bounds__(256) scan_kernel(
    const float* __restrict__ dt, const float* __restrict__ uc,
    const float* __restrict__ dbc, const float* __restrict__ xz,
    const float* __restrict__ A_log, const float* __restrict__ Dskip,
    float* __restrict__ yg)
{
    int b    = blockIdx.y;
    int c    = blockIdx.x * 64 + (threadIdx.x >> 2);
    int s0   = (threadIdx.x & 3) * 4;

    float A0 = -__expf(A_log[c*DS + s0 + 0]);
    float A1 = -__expf(A_log[c*DS + s0 + 1]);
    float A2 = -__expf(A_log[c*DS + s0 + 2]);
    float A3 = -__expf(A_log[c*DS + s0 + 3]);
    float Dv = Dskip[c];

    const float* dtp = dt  + (size_t)b*LL*DI + c;
    const float* ucp = uc  + (size_t)b*LL*DI + c;
    const float* zp  = xz  + (size_t)b*LL*(2*DI) + DI + c;
    const float* bcp = dbc + (size_t)b*LL*DBC_LD + DTR + s0;   // Bs at +64, Cs at +80
    float*       yp  = yg  + (size_t)b*LL*DI + c;

    float h0 = 0.f, h1 = 0.f, h2 = 0.f, h3 = 0.f;

    for (int t = 0; t < LL; t++) {
        float dtv = *dtp;
        float uv  = *ucp;
        float4 Bv = *(const float4*)(bcp);
        float4 Cv = *(const float4*)(bcp + DS);
        float zv  = *zp;

        float du = dtv * uv;
        h0 = h0 * __expf(dtv * A0) + du * Bv.x;
        h1 = h1 * __expf(dtv * A1) + du * Bv.y;
        h2 = h2 * __expf(dtv * A2) + du * Bv.z;
        h3 = h3 * __expf(dtv * A3) + du * Bv.w;

        float acc = h0*Cv.x + h1*Cv.y + h2*Cv.z + h3*Cv.w;
        acc += __shfl_xor_sync(0xffffffffu, acc, 1);
        acc += __shfl_xor_sync(0xffffffffu, acc, 2);

        if ((threadIdx.x & 3) == 0) {
            float y = acc + uv * Dv;
            *yp = y * (zv / (1.f + __expf(-zv)));
        }
        dtp += DI; ucp += DI; zp += 2*DI; bcp += DBC_LD; yp += DI;
    }
}

// ---------------- launcher ----------------
extern "C" void kernel_launch(void* const* d_in, const int* in_sizes, int n_in,
                              void* d_out, int out_size)
{
    const float* x      = (const float*)d_in[0];
    const float* ln_g   = (const float*)d_in[1];
    const float* ln_b   = (const float*)d_in[2];
    const float* W_in   = (const float*)d_in[3];
    const float* conv_w = (const float*)d_in[4];
    const float* conv_b = (const float*)d_in[5];
    const float* W_x    = (const float*)d_in[6];
    const float* W_dt   = (const float*)d_in[7];
    const float* b_dt   = (const float*)d_in[8];
    const float* A_log  = (const float*)d_in[9];
    const float* Dskip  = (const float*)d_in[10];
    const float* W_out  = (const float*)d_in[11];
    float* out = (float*)d_out;

    float *p_xn, *p_xz, *p_uc, *p_wxp, *p_dbc, *p_dt, *p_yg;
    cudaGetSymbolAddress((void**)&p_xn,  g_xn);
    cudaGetSymbolAddress((void**)&p_xz,  g_xz);
    cudaGetSymbolAddress((void**)&p_uc,  g_uc);
    cudaGetSymbolAddress((void**)&p_wxp, g_wxp);
    cudaGetSymbolAddress((void**)&p_dbc, g_dbc);
    cudaGetSymbolAddress((void**)&p_dt,  g_dt);
    cudaGetSymbolAddress((void**)&p_yg,  g_yg);

    // 1) pad W_x
    pad_wx_kernel<<<(DI*DBC_LD + 255)/256, 256>>>(W_x, p_wxp);

    // 2) LayerNorm
    ln_kernel<<<ROWS, 256>>>(x, ln_g, ln_b, p_xn);

    // 3) xz = xn @ W_in     (8192 x 1024 x 4096)
    {
        dim3 grid(2*DI/128, ROWS/128);
        sgemm_kernel<0><<<grid, 256>>>(ROWS, 2*DI, DM,
                                       p_xn, DM, W_in, 2*DI, p_xz, 2*DI,
                                       nullptr, nullptr, 0);
    }

    // 4) depthwise conv + SiLU  -> uc
    conv_silu_kernel<<<(ROWS*DI + 255)/256, 256>>>(p_xz, conv_w, conv_b, p_uc);

    // 5) dbc = uc @ W_x_pad   (8192 x 2048 x 128)
    {
        dim3 grid(DBC_LD/128, ROWS/128);
        sgemm_kernel<0><<<grid, 256>>>(ROWS, DBC_LD, DI,
                                       p_uc, DI, p_wxp, DBC_LD, p_dbc, DBC_LD,
                                       nullptr, nullptr, 0);
    }

    // 6) dt = softplus(dt_r @ W_dt + b_dt)   (8192 x 64 x 2048)
    {
        dim3 grid(DI/128, ROWS/128);
        sgemm_kernel<1><<<grid, 256>>>(ROWS, DI, DTR,
                                       p_dbc, DBC_LD, W_dt, DI, p_dt, DI,
                                       b_dt, nullptr, 0);
    }

    // 7) selective scan + Dskip + z-gating -> yg
    {
        dim3 grid(DI/64, BB);
        scan_kernel<<<grid, 256>>>(p_dt, p_uc, p_dbc, p_xz, A_log, Dskip, p_yg);
    }

    // 8) out = x + yg @ W_out   (8192 x 2048 x 1024)
    {
        dim3 grid(DM/128, ROWS/128);
        sgemm_kernel<2><<<grid, 256>>>(ROWS, DM, DI,
                                       p_yg, DI, W_out, DM, out, DM,
                                       nullptr, x, DM);
    }
}

// round 3
// speedup vs baseline: 1.6415x; 1.6415x over previous
#include <cuda_runtime.h>
#include <math.h>
#include <stdint.h>

// ---------------- problem constants ----------------
#define BB      4
#define LL      2048
#define DM      1024          // d_model
#define DI      2048          // d_inner
#define DS      16            // d_state
#define DTR     64            // dt_rank
#define ROWS    (BB*LL)       // 8192 token rows
#define DBC_LD  128           // padded (dt_rank + 2*d_state = 96 -> 128)

// ---------------- scratch (static device memory; no cudaMalloc allowed) ----
__device__ float g_xn [ (size_t)ROWS*DM ];        // 32 MB
__device__ float g_xz [ (size_t)ROWS*2*DI ];      // 128 MB  (u | z)
__device__ float g_uc [ (size_t)ROWS*DI ];        // 64 MB
__device__ float g_dbc[ (size_t)ROWS*DBC_LD ];    // 4 MB
__device__ float g_dt [ (size_t)ROWS*DI ];        // 64 MB
__device__ float g_yg [ (size_t)ROWS*DI ];        // 64 MB
// transposed weights (B operands, K-major)
__device__ float g_wiT[ (size_t)(2*DI)*DM ];      // W_in^T  : 4096 x 1024
__device__ float g_wxT[ (size_t)DBC_LD*DI ];      // W_x^T   : 128  x 2048 (rows 96..127 zero)
__device__ float g_wdT[ (size_t)DI*DTR ];         // W_dt^T  : 2048 x 64
__device__ float g_woT[ (size_t)DM*DI ];          // W_out^T : 1024 x 2048

__device__ __forceinline__ uint32_t f2tf32(float f) {
    uint32_t u;
    asm("cvt.rna.tf32.f32 %0, %1;" : "=r"(u) : "f"(f));
    return u;
}
__device__ __forceinline__ float softplus_f(float x) {
    return (x > 20.f) ? x : log1pf(__expf(x));
}
__device__ __forceinline__ void mma_tf32(float* d, const uint32_t* a, const uint32_t* b) {
    asm volatile(
        "mma.sync.aligned.m16n8k8.row.col.f32.tf32.tf32.f32 "
        "{%0,%1,%2,%3}, {%4,%5,%6,%7}, {%8,%9}, {%0,%1,%2,%3};"
        : "+f"(d[0]), "+f"(d[1]), "+f"(d[2]), "+f"(d[3])
        : "r"(a[0]), "r"(a[1]), "r"(a[2]), "r"(a[3]), "r"(b[0]), "r"(b[1]));
}

// ================= LayerNorm =================
__global__ void __launch_bounds__(256) ln_kernel(
    const float* __restrict__ x, const float* __restrict__ g,
    const float* __restrict__ b, float* __restrict__ out)
{
    int row = blockIdx.x;
    int tid = threadIdx.x;
    const float4* xr = (const float4*)(x + (size_t)row*DM);
    float4 v = xr[tid];
    float s  = v.x + v.y + v.z + v.w;
    float ss = v.x*v.x + v.y*v.y + v.z*v.z + v.w*v.w;
    #pragma unroll
    for (int o = 16; o; o >>= 1) {
        s  += __shfl_xor_sync(0xffffffffu, s,  o);
        ss += __shfl_xor_sync(0xffffffffu, ss, o);
    }
    __shared__ float sb[8], ssb[8];
    if ((tid & 31) == 0) { sb[tid>>5] = s; ssb[tid>>5] = ss; }
    __syncthreads();
    float tot = 0.f, tot2 = 0.f;
    #pragma unroll
    for (int i = 0; i < 8; i++) { tot += sb[i]; tot2 += ssb[i]; }
    float mu  = tot * (1.0f/DM);
    float var = tot2 * (1.0f/DM) - mu*mu;
    float rs  = rsqrtf(var + 1e-5f);
    float4 gv = ((const float4*)g)[tid];
    float4 bv = ((const float4*)b)[tid];
    float4 o;
    o.x = (v.x-mu)*rs*gv.x + bv.x;
    o.y = (v.y-mu)*rs*gv.y + bv.y;
    o.z = (v.z-mu)*rs*gv.z + bv.z;
    o.w = (v.w-mu)*rs*gv.w + bv.w;
    ((float4*)(out + (size_t)row*DM))[tid] = o;
}

// ================= transpose with zero-pad of extra output rows ========
__global__ void transpose_kernel(const float* __restrict__ in, float* __restrict__ out,
                                 int R, int C)
{
    __shared__ float t[32][33];
    int r0 = blockIdx.x*32, c0 = blockIdx.y*32;
    int tx = threadIdx.x, ty = threadIdx.y;
    #pragma unroll
    for (int j = 0; j < 32; j += 8) {
        int c = c0 + tx;
        t[ty+j][tx] = (c < C) ? in[(size_t)(r0+ty+j)*C + c] : 0.f;
    }
    __syncthreads();
    #pragma unroll
    for (int j = 0; j < 32; j += 8)
        out[(size_t)(c0+ty+j)*R + r0 + tx] = t[tx][ty+j];
}

// ================= depthwise causal conv (k=4) + SiLU =================
__global__ void __launch_bounds__(256) conv_silu_kernel(
    const float* __restrict__ xz, const float* __restrict__ w,
    const float* __restrict__ cb, float* __restrict__ uc)
{
    int idx = blockIdx.x * blockDim.x + threadIdx.x;
    if (idx >= ROWS*DI) return;
    int d   = idx % DI;
    int row = idx / DI;
    int l   = row % LL;
    const float* up = xz + (size_t)row*(2*DI) + d;
    float4 wv = *(const float4*)(w + d*4);
    float acc = cb[d];
    if (l >= 3) acc += wv.x * up[-3*2*DI];
    if (l >= 2) acc += wv.y * up[-2*2*DI];
    if (l >= 1) acc += wv.z * up[-1*2*DI];
    acc += wv.w * up[0];
    uc[idx] = acc / (1.f + __expf(-acc));
}

// ================= mma.sync tf32 GEMM =================
// C[M, N] = A[M, K] (row-major, lda) @ Bt[N, K]^T (row-major K-major, ldb)
// CTA tile 128x128, BK=32, 8 warps (warp tile 64x32), double-buffered SMEM.
// EPI: 0 plain, 1 softplus(acc + bias[n]), 2 acc + res[m][n] (ldr == ldc)
#define SSTR 36   // smem row stride in floats (32 + 4 pad)

template<int EPI>
__global__ void __launch_bounds__(256) mma_gemm(
    int K,
    const float* __restrict__ A, int lda,
    const float* __restrict__ Bt, int ldb,
    float* __restrict__ C, int ldc,
    const float* __restrict__ bias,
    const float* __restrict__ res)
{
    extern __shared__ uint32_t smem[];
    uint32_t* As = smem;                    // [2][128*SSTR]
    uint32_t* Bs = smem + 2*128*SSTR;       // [2][128*SSTR]

    const int tid  = threadIdx.x;
    const int lane = tid & 31, wid = tid >> 5;
    const int warp_m = wid >> 2, warp_n = wid & 3;
    const int bm = blockIdx.y, bn = blockIdx.x;

    const int sm = tid >> 3;        // 0..127  (staging row)
    const int sq = tid & 7;         // 0..7    (staging quad: 4 floats)

    const float* Ag = A  + (size_t)(bm*128 + sm)*lda + sq*4;
    const float* Bg = Bt + (size_t)(bn*128 + sm)*ldb + sq*4;

    float4 ar[4], br[4];
    auto ldg = [&](int kt) {
        #pragma unroll
        for (int i = 0; i < 4; i++) ar[i] = *(const float4*)(Ag + (size_t)i*32*lda + kt*32);
        #pragma unroll
        for (int i = 0; i < 4; i++) br[i] = *(const float4*)(Bg + (size_t)i*32*ldb + kt*32);
    };
    auto sts = [&](int s) {
        uint32_t* a = As + s*128*SSTR + sm*SSTR + sq*4;
        uint32_t* b = Bs + s*128*SSTR + sm*SSTR + sq*4;
        #pragma unroll
        for (int i = 0; i < 4; i++) {
            a[i*32*SSTR + 0] = f2tf32(ar[i].x);
            a[i*32*SSTR + 1] = f2tf32(ar[i].y);
            a[i*32*SSTR + 2] = f2tf32(ar[i].z);
            a[i*32*SSTR + 3] = f2tf32(ar[i].w);
            b[i*32*SSTR + 0] = f2tf32(br[i].x);
            b[i*32*SSTR + 1] = f2tf32(br[i].y);
            b[i*32*SSTR + 2] = f2tf32(br[i].z);
            b[i*32*SSTR + 3] = f2tf32(br[i].w);
        }
    };

    float acc[4][4][4] = {};

    const int KT = K / 32;
    ldg(0); sts(0);
    __syncthreads();

    for (int kt = 0; kt < KT; kt++) {
        int s = kt & 1;
        if (kt + 1 < KT) ldg(kt + 1);

        const uint32_t* as = As + s*128*SSTR;
        const uint32_t* bs = Bs + s*128*SSTR;
        #pragma unroll
        for (int k8 = 0; k8 < 4; k8++) {
            int kc = k8*8 + (lane & 3);
            uint32_t afr[4][4], bfr[4][2];
            #pragma unroll
            for (int mi = 0; mi < 4; mi++) {
                int r0 = warp_m*64 + mi*16 + (lane >> 2);
                afr[mi][0] = as[r0*SSTR + kc];
                afr[mi][1] = as[(r0+8)*SSTR + kc];
                afr[mi][2] = as[r0*SSTR + kc + 4];
                afr[mi][3] = as[(r0+8)*SSTR + kc + 4];
            }
            #pragma unroll
            for (int ni = 0; ni < 4; ni++) {
                int c0 = warp_n*32 + ni*8 + (lane >> 2);
                bfr[ni][0] = bs[c0*SSTR + kc];
                bfr[ni][1] = bs[c0*SSTR + kc + 4];
            }
            #pragma unroll
            for (int mi = 0; mi < 4; mi++)
                #pragma unroll
                for (int ni = 0; ni < 4; ni++)
                    mma_tf32(acc[mi][ni], afr[mi], bfr[ni]);
        }

        if (kt + 1 < KT) sts(s ^ 1);
        __syncthreads();
    }

    // ---- epilogue ----
    #pragma unroll
    for (int mi = 0; mi < 4; mi++) {
        int row = bm*128 + warp_m*64 + mi*16 + (lane >> 2);
        #pragma unroll
        for (int ni = 0; ni < 4; ni++) {
            int col = bn*128 + warp_n*32 + ni*8 + (lane & 3)*2;
            float2 lo = make_float2(acc[mi][ni][0], acc[mi][ni][1]);
            float2 hi = make_float2(acc[mi][ni][2], acc[mi][ni][3]);
            if (EPI == 1) {
                float2 bb = *(const float2*)(bias + col);
                lo.x = softplus_f(lo.x + bb.x); lo.y = softplus_f(lo.y + bb.y);
                hi.x = softplus_f(hi.x + bb.x); hi.y = softplus_f(hi.y + bb.y);
            } else if (EPI == 2) {
                float2 r0 = *(const float2*)(res + (size_t)row*ldc + col);
                float2 r1 = *(const float2*)(res + (size_t)(row+8)*ldc + col);
                lo.x += r0.x; lo.y += r0.y;
                hi.x += r1.x; hi.y += r1.y;
            }
            *(float2*)(C + (size_t)row*ldc + col)     = lo;
            *(float2*)(C + (size_t)(row+8)*ldc + col) = hi;
        }
    }
}

// ================= selective scan (serial in L) + gating =================
__global__ void __launch_bounds__(256) scan_kernel(
    const float* __restrict__ dt, const float* __restrict__ uc,
    const float* __restrict__ dbc, const float* __restrict__ xz,
    const float* __restrict__ A_log, const float* __restrict__ Dskip,
    float* __restrict__ yg)
{
    int b    = blockIdx.y;
    int c    = blockIdx.x * 64 + (threadIdx.x >> 2);
    int s0   = (threadIdx.x & 3) * 4;

    float A0 = -__expf(A_log[c*DS + s0 + 0]);
    float A1 = -__expf(A_log[c*DS + s0 + 1]);
    float A2 = -__expf(A_log[c*DS + s0 + 2]);
    float A3 = -__expf(A_log[c*DS + s0 + 3]);
    float Dv = Dskip[c];

    const float* dtp = dt  + (size_t)b*LL*DI + c;
    const float* ucp = uc  + (size_t)b*LL*DI + c;
    const float* zp  = xz  + (size_t)b*LL*(2*DI) + DI + c;
    const float* bcp = dbc + (size_t)b*LL*DBC_LD + DTR + s0;
    float*       yp  = yg  + (size_t)b*LL*DI + c;

    float h0 = 0.f, h1 = 0.f, h2 = 0.f, h3 = 0.f;

    for (int t = 0; t < LL; t++) {
        float dtv = *dtp;
        float uv  = *ucp;
        float4 Bv = *(const float4*)(bcp);
        float4 Cv = *(const float4*)(bcp + DS);
        float zv  = *zp;

        float du = dtv * uv;
        h0 = h0 * __expf(dtv * A0) + du * Bv.x;
        h1 = h1 * __expf(dtv * A1) + du * Bv.y;
        h2 = h2 * __expf(dtv * A2) + du * Bv.z;
        h3 = h3 * __expf(dtv * A3) + du * Bv.w;

        float acc = h0*Cv.x + h1*Cv.y + h2*Cv.z + h3*Cv.w;
        acc += __shfl_xor_sync(0xffffffffu, acc, 1);
        acc += __shfl_xor_sync(0xffffffffu, acc, 2);

        if ((threadIdx.x & 3) == 0) {
            float y = acc + uv * Dv;
            *yp = y * (zv / (1.f + __expf(-zv)));
        }
        dtp += DI; ucp += DI; zp += 2*DI; bcp += DBC_LD; yp += DI;
    }
}

// ================= launcher =================
extern "C" void kernel_launch(void* const* d_in, const int* in_sizes, int n_in,
                              void* d_out, int out_size)
{
    const float* x      = (const float*)d_in[0];
    const float* ln_g   = (const float*)d_in[1];
    const float* ln_b   = (const float*)d_in[2];
    const float* W_in   = (const float*)d_in[3];
    const float* conv_w = (const float*)d_in[4];
    const float* conv_b = (const float*)d_in[5];
    const float* W_x    = (const float*)d_in[6];
    const float* W_dt   = (const float*)d_in[7];
    const float* b_dt   = (const float*)d_in[8];
    const float* A_log  = (const float*)d_in[9];
    const float* Dskip  = (const float*)d_in[10];
    const float* W_out  = (const float*)d_in[11];
    float* out = (float*)d_out;

    float *p_xn, *p_xz, *p_uc, *p_dbc, *p_dt, *p_yg;
    float *p_wiT, *p_wxT, *p_wdT, *p_woT;
    cudaGetSymbolAddress((void**)&p_xn,  g_xn);
    cudaGetSymbolAddress((void**)&p_xz,  g_xz);
    cudaGetSymbolAddress((void**)&p_uc,  g_uc);
    cudaGetSymbolAddress((void**)&p_dbc, g_dbc);
    cudaGetSymbolAddress((void**)&p_dt,  g_dt);
    cudaGetSymbolAddress((void**)&p_yg,  g_yg);
    cudaGetSymbolAddress((void**)&p_wiT, g_wiT);
    cudaGetSymbolAddress((void**)&p_wxT, g_wxT);
    cudaGetSymbolAddress((void**)&p_wdT, g_wdT);
    cudaGetSymbolAddress((void**)&p_woT, g_woT);

    const int SMEM = 4 * 128 * SSTR * 4;   // 73728 bytes
    cudaFuncSetAttribute(mma_gemm<0>, cudaFuncAttributeMaxDynamicSharedMemorySize, SMEM);
    cudaFuncSetAttribute(mma_gemm<1>, cudaFuncAttributeMaxDynamicSharedMemorySize, SMEM);
    cudaFuncSetAttribute(mma_gemm<2>, cudaFuncAttributeMaxDynamicSharedMemorySize, SMEM);

    dim3 tb(32, 8);
    // weight transposes (B operands, K-major)
    transpose_kernel<<<dim3(DM/32,   (2*DI)/32), tb>>>(W_in,  p_wiT, DM, 2*DI);
    transpose_kernel<<<dim3(DI/32,   DBC_LD/32), tb>>>(W_x,   p_wxT, DI, 96);
    transpose_kernel<<<dim3(DTR/32,  DI/32),     tb>>>(W_dt,  p_wdT, DTR, DI);
    transpose_kernel<<<dim3(DI/32,   DM/32),     tb>>>(W_out, p_woT, DI, DM);

    // LayerNorm
    ln_kernel<<<ROWS, 256>>>(x, ln_g, ln_b, p_xn);

    // GEMM1: xz = xn @ W_in   (8192 x 4096 x 1024)
    mma_gemm<0><<<dim3(2*DI/128, ROWS/128), 256, SMEM>>>(
        DM, p_xn, DM, p_wiT, DM, p_xz, 2*DI, nullptr, nullptr);

    // conv + SiLU
    conv_silu_kernel<<<(ROWS*DI + 255)/256, 256>>>(p_xz, conv_w, conv_b, p_uc);

    // GEMM2: dbc = uc @ W_x   (8192 x 128 x 2048), cols 96..127 = 0
    mma_gemm<0><<<dim3(1, ROWS/128), 256, SMEM>>>(
        DI, p_uc, DI, p_wxT, DI, p_dbc, DBC_LD, nullptr, nullptr);

    // GEMM3: dt = softplus(dbc[:, :64] @ W_dt + b_dt)   (8192 x 2048 x 64)
    mma_gemm<1><<<dim3(DI/128, ROWS/128), 256, SMEM>>>(
        DTR, p_dbc, DBC_LD, p_wdT, DTR, p_dt, DI, b_dt, nullptr);

    // selective scan + Dskip + z-gating
    scan_kernel<<<dim3(DI/64, BB), 256>>>(p_dt, p_uc, p_dbc, p_xz, A_log, Dskip, p_yg);

    // GEMM4: out = x + yg @ W_out   (8192 x 1024 x 2048)
    mma_gemm<2><<<dim3(DM/128, ROWS/128), 256, SMEM>>>(
        DI, p_yg, DI, p_woT, DI, out, DM, nullptr, x);
}